// round 4
// baseline (speedup 1.0000x reference)
#include <cuda_runtime.h>
#include <math.h>

#define NB      32
#define SAMPLES 5000
#define HW      (512 * 1024)
#define TOTAL   (NB * SAMPLES)          // 160000 pairs
#define TOTAL2  (TOTAL * 2)             // 320000 threads (one per pair-side)
#define SIGMA   0.03f
#define EPS     1e-6f

#define THREADS 256
#define BLOCKS  (TOTAL2 / THREADS)      // 1250 exactly

// zero-initialized at load; reset by last block each call (graph-safe)
__device__ float        g_acc[3];       // [0]=equal, [1]=unequal, [2]=valid
__device__ unsigned int g_count;

__global__ void __launch_bounds__(THREADS) rl_fused2_kernel(
    const float* __restrict__ pred,
    const float* __restrict__ targ,
    const int*   __restrict__ mask,     // bool upcast to int32 by harness
    const int*   __restrict__ idxA,
    const int*   __restrict__ idxB,
    float*       __restrict__ out)
{
    int i = blockIdx.x * blockDim.x + threadIdx.x;   // always < TOTAL2

    int pair = i >> 1;
    int side = i & 1;                                // 0 = A-lane, 1 = B-lane
    int n    = pair / SAMPLES;

    const int* idxArr = side ? idxB : idxA;
    int idx = idxArr[pair];
    long long g = (long long)n * (long long)HW + (long long)idx;

    // round trip 1: own mask
    int m      = mask[g];
    int mOther = __shfl_xor_sync(0xffffffffu, m, 1);
    bool cm = (m != 0) && (mOther != 0);

    // round trip 2: targ/pred only for valid pairs (~25%)
    float t = 1.0f, p = 0.0f;
    if (cm) {
        t = targ[g];
        p = pred[g];
    }
    float tO = __shfl_xor_sync(0xffffffffu, t, 1);
    float pO = __shfl_xor_sync(0xffffffffu, p, 1);

    float eq = 0.0f, uneq = 0.0f, valid = 0.0f;
    if (side == 0 && cm) {               // even lane owns the pair's loss
        float tA = t,  tB = tO;
        float pA = p,  pB = pO;

        float ratio = tA / (tB + EPS);
        const float hi = 1.0f + SIGMA;
        const float lo = 1.0f / (1.0f + SIGMA);
        bool mask_eq = (ratio < hi) && (ratio > lo);

        valid = 1.0f;
        if (mask_eq) {
            float d = pA - pB;
            eq = d * d;
        } else {
            float label = (ratio >= hi) ? 1.0f : -1.0f;
            float x = (pB - pA) * label;
            uneq = (x > 20.0f) ? x : log1pf(expf(x));
        }
    }

    // --- block reduction of (eq, uneq, valid) ---
    #pragma unroll
    for (int off = 16; off > 0; off >>= 1) {
        eq    += __shfl_down_sync(0xffffffffu, eq,    off);
        uneq  += __shfl_down_sync(0xffffffffu, uneq,  off);
        valid += __shfl_down_sync(0xffffffffu, valid, off);
    }

    __shared__ float s_eq[8], s_uneq[8], s_valid[8];
    __shared__ bool  s_last;
    int lane = threadIdx.x & 31;
    int wid  = threadIdx.x >> 5;
    if (lane == 0) {
        s_eq[wid]    = eq;
        s_uneq[wid]  = uneq;
        s_valid[wid] = valid;
    }
    __syncthreads();

    if (wid == 0) {
        eq    = (lane < (THREADS / 32)) ? s_eq[lane]    : 0.0f;
        uneq  = (lane < (THREADS / 32)) ? s_uneq[lane]  : 0.0f;
        valid = (lane < (THREADS / 32)) ? s_valid[lane] : 0.0f;
        #pragma unroll
        for (int off = 4; off > 0; off >>= 1) {
            eq    += __shfl_down_sync(0xffffffffu, eq,    off);
            uneq  += __shfl_down_sync(0xffffffffu, uneq,  off);
            valid += __shfl_down_sync(0xffffffffu, valid, off);
        }
        if (lane == 0) {
            atomicAdd(&g_acc[0], eq);
            atomicAdd(&g_acc[1], uneq);
            atomicAdd(&g_acc[2], valid);
            __threadfence();
            unsigned ticket = atomicAdd(&g_count, 1u);
            s_last = (ticket == (unsigned)(gridDim.x - 1));
        }
    }
    __syncthreads();

    // last block finalizes and resets state for next graph replay
    if (s_last && threadIdx.x == 0) {
        float e = g_acc[0], u = g_acc[1], v = g_acc[2];
        out[0] = (e + u) / (v + EPS);    // ALPHA = LOSS_WEIGHT = 1
        g_acc[0] = 0.0f;
        g_acc[1] = 0.0f;
        g_acc[2] = 0.0f;
        __threadfence();
        g_count = 0u;
    }
}

extern "C" void kernel_launch(void* const* d_in, const int* in_sizes, int n_in,
                              void* d_out, int out_size)
{
    const float* pred = (const float*)d_in[0];
    const float* targ = (const float*)d_in[1];
    const int*   mask = (const int*)d_in[2];
    const int*   idxA = (const int*)d_in[3];
    const int*   idxB = (const int*)d_in[4];
    float* out = (float*)d_out;

    rl_fused2_kernel<<<BLOCKS, THREADS>>>(pred, targ, mask, idxA, idxB, out);
}

// round 5
// speedup vs baseline: 1.0172x; 1.0172x over previous
#include <cuda_runtime.h>
#include <math.h>

#define NB      32
#define SAMPLES 5000
#define HW      (512 * 1024)
#define TOTAL   (NB * SAMPLES)          // 160000 pairs
#define TOTAL2  (TOTAL * 2)             // 320000 threads (one per pair-side)
#define SIGMA   0.03f
#define EPS     1e-6f

#define THREADS 256
#define BLOCKS  (TOTAL2 / THREADS)      // 1250 exactly

// zero-initialized at load; reset by last block each call (graph-safe)
__device__ float        g_acc[3];       // [0]=equal, [1]=unequal, [2]=valid
__device__ unsigned int g_count;

__global__ void __launch_bounds__(THREADS) rl_fused3_kernel(
    const float* __restrict__ pred,
    const float* __restrict__ targ,
    const int*   __restrict__ mask,     // bool upcast to int32 by harness
    const int*   __restrict__ idxA,
    const int*   __restrict__ idxB,
    float*       __restrict__ out)
{
    int i = blockIdx.x * blockDim.x + threadIdx.x;   // < TOTAL2 always

    int pair = i >> 1;
    int side = i & 1;                                // 0 = A-lane, 1 = B-lane
    int n    = pair / SAMPLES;
    long long base = (long long)n * (long long)HW;

    // both threads of the pair load BOTH indices (coalesced; adjacent lanes
    // read identical addresses -> merged in L1)
    int a = idxA[pair];
    int b = idxB[pair];
    long long gA = base + (long long)a;
    long long gB = base + (long long)b;
    long long g  = side ? gB : gA;

    // round trip 1: both masks (adjacent lanes hit the same sectors -> merged)
    int mA = mask[gA];
    int mB = mask[gB];
    bool cm = (mA != 0) && (mB != 0);

    // round trip 2: own targ/pred, only for valid pairs (~25%).
    // No warp-wide sync between trips: each thread proceeds independently.
    float t = 1.0f, p = 0.0f;
    if (cm) {
        t = targ[g];
        p = pred[g];
    }
    // single exchange at the end (dummy values fine for invalid pairs)
    float tO = __shfl_xor_sync(0xffffffffu, t, 1);
    float pO = __shfl_xor_sync(0xffffffffu, p, 1);

    float eq = 0.0f, uneq = 0.0f, valid = 0.0f;
    if (side == 0 && cm) {               // even lane owns the pair's loss
        float tA = t,  tB = tO;
        float pA = p,  pB = pO;

        float ratio = tA / (tB + EPS);
        const float hi = 1.0f + SIGMA;
        const float lo = 1.0f / (1.0f + SIGMA);
        bool mask_eq = (ratio < hi) && (ratio > lo);

        valid = 1.0f;
        if (mask_eq) {
            float d = pA - pB;
            eq = d * d;
        } else {
            float label = (ratio >= hi) ? 1.0f : -1.0f;
            float x = (pB - pA) * label;
            uneq = (x > 20.0f) ? x : log1pf(expf(x));
        }
    }

    // --- block reduction of (eq, uneq, valid) ---
    #pragma unroll
    for (int off = 16; off > 0; off >>= 1) {
        eq    += __shfl_down_sync(0xffffffffu, eq,    off);
        uneq  += __shfl_down_sync(0xffffffffu, uneq,  off);
        valid += __shfl_down_sync(0xffffffffu, valid, off);
    }

    __shared__ float s_eq[8], s_uneq[8], s_valid[8];
    __shared__ bool  s_last;
    int lane = threadIdx.x & 31;
    int wid  = threadIdx.x >> 5;
    if (lane == 0) {
        s_eq[wid]    = eq;
        s_uneq[wid]  = uneq;
        s_valid[wid] = valid;
    }
    __syncthreads();

    if (wid == 0) {
        eq    = (lane < (THREADS / 32)) ? s_eq[lane]    : 0.0f;
        uneq  = (lane < (THREADS / 32)) ? s_uneq[lane]  : 0.0f;
        valid = (lane < (THREADS / 32)) ? s_valid[lane] : 0.0f;
        #pragma unroll
        for (int off = 4; off > 0; off >>= 1) {
            eq    += __shfl_down_sync(0xffffffffu, eq,    off);
            uneq  += __shfl_down_sync(0xffffffffu, uneq,  off);
            valid += __shfl_down_sync(0xffffffffu, valid, off);
        }
        if (lane == 0) {
            atomicAdd(&g_acc[0], eq);
            atomicAdd(&g_acc[1], uneq);
            atomicAdd(&g_acc[2], valid);
            __threadfence();
            unsigned ticket = atomicAdd(&g_count, 1u);
            s_last = (ticket == (unsigned)(gridDim.x - 1));
        }
    }
    __syncthreads();

    // last block finalizes and resets state for next graph replay
    if (s_last && threadIdx.x == 0) {
        float e = g_acc[0], u = g_acc[1], v = g_acc[2];
        out[0] = (e + u) / (v + EPS);    // ALPHA = LOSS_WEIGHT = 1
        g_acc[0] = 0.0f;
        g_acc[1] = 0.0f;
        g_acc[2] = 0.0f;
        __threadfence();
        g_count = 0u;
    }
}

extern "C" void kernel_launch(void* const* d_in, const int* in_sizes, int n_in,
                              void* d_out, int out_size)
{
    const float* pred = (const float*)d_in[0];
    const float* targ = (const float*)d_in[1];
    const int*   mask = (const int*)d_in[2];
    const int*   idxA = (const int*)d_in[3];
    const int*   idxB = (const int*)d_in[4];
    float* out = (float*)d_out;

    rl_fused3_kernel<<<BLOCKS, THREADS>>>(pred, targ, mask, idxA, idxB, out);
}